// round 15
// baseline (speedup 1.0000x reference)
#include <cuda_runtime.h>
#include <math.h>

#define TPB   256
#define HS    (64 * 512)
#define XSTF  132
#define XSN   (64 * XSTF)            // 8448 floats per x buffer

// ---------------- device scratch ----------------
__device__ float g_Wr[3072 * 2048];       // slabs: enc0(512K)|enc1(1024K)|dec0(512K)|dec1(1024K), [cta][k][16]
__device__ float g_hist[513 * HS];        // h0 history: enc t=0..256, dec 257..512
__device__ float g_h1[2 * HS];            // h1 ping-pong (s-parity, continuous enc->dec)
__device__ float g_c0[HS];
__device__ float g_c1[HS];
__device__ float g_en_last[HS];
__device__ float g_embz_enc[128 * 2048];
__device__ float g_embz_dec[128 * 2048];
__device__ float g_enlz[64 * 2048];
__device__ float g_dec_out[64 * 256 * 512];
__device__ __align__(128) unsigned g_arr0[32];
__device__ __align__(128) unsigned g_flag0[32];
__device__ __align__(128) unsigned g_arr1[32];
__device__ __align__(128) unsigned g_flag1[32];

__device__ __forceinline__ float sigmoidf_(float x) { return 1.0f / (1.0f + __expf(-x)); }

// group barrier: arrive on own counter; last sets flag (release); others poll (acquire)
__device__ __forceinline__ void group_sync(unsigned* arr, unsigned* flag, unsigned step, unsigned gsz) {
    __syncthreads();
    if (threadIdx.x == 0) {
        __threadfence();
        unsigned prev = atomicAdd(arr, 1u);
        if (prev == step * gsz - 1u) {
            asm volatile("st.release.gpu.global.u32 [%0], %1;" :: "l"(flag), "r"(step) : "memory");
        } else {
            unsigned v;
            while (true) {
                asm volatile("ld.acquire.gpu.global.u32 %0, [%1];" : "=r"(v) : "l"(flag) : "memory");
                if ((int)(v - step) >= 0) break;
                __nanosleep(32);
            }
        }
    }
    __syncthreads();
}

// pure wait on another group's flag
__device__ __forceinline__ void wait_flag(unsigned* flag, unsigned target) {
    __syncthreads();
    if (threadIdx.x == 0) {
        unsigned v;
        while (true) {
            asm volatile("ld.acquire.gpu.global.u32 %0, [%1];" : "=r"(v) : "l"(flag) : "memory");
            if ((int)(v - target) >= 0) break;
            __nanosleep(32);
        }
    }
    __syncthreads();
}

// fill one 128-k chunk: thread (m = tid>>2, cp = tid&3) loads 8 float4 of row m
__device__ __forceinline__ void fill_chunk(float* __restrict__ xs, const float* __restrict__ src,
                                           int m, int q0) {
    float4 v[8];
    const float4* p = reinterpret_cast<const float4*>(src + m * 512);
#pragma unroll
    for (int j = 0; j < 8; ++j) v[j] = __ldcg(p + q0 + j);
    float4* row = reinterpret_cast<float4*>(xs + m * XSTF);
#pragma unroll
    for (int j = 0; j < 8; ++j) row[q0 + j] = v[j];
}

// 128 k's: thread owns 4 gate-cols of one unit (float4 acc); 32 x-LDS + 128 w-LDS + 512 FMA
__device__ __forceinline__ void compute_chunk(const float* __restrict__ xrow,
                                              const float* __restrict__ wsbase,
                                              int cp, float4& acc) {
    const float4* xr = reinterpret_cast<const float4*>(xrow);
    const float4* wp = reinterpret_cast<const float4*>(wsbase) + cp;
#pragma unroll
    for (int kq = 0; kq < 32; ++kq) {
        float4 xv = xr[kq];
        float xa[4] = {xv.x, xv.y, xv.z, xv.w};
#pragma unroll
        for (int q = 0; q < 4; ++q) {
            float4 w = wp[(kq * 4 + q) * 4];
            acc.x = fmaf(xa[q], w.x, acc.x);
            acc.y = fmaf(xa[q], w.y, acc.y);
            acc.z = fmaf(xa[q], w.z, acc.z);
            acc.w = fmaf(xa[q], w.w, acc.w);
        }
    }
}

// ---------------- init ----------------
__global__ void init_kernel() {
    int idx = blockIdx.x * blockDim.x + threadIdx.x;
    int stride = gridDim.x * blockDim.x;
    for (int i = idx; i < HS; i += stride) g_hist[i] = 0.f;          // hist[0]
    for (int i = idx; i < 2 * HS; i += stride) g_h1[i] = 0.f;
    for (int i = idx; i < HS; i += stride) g_en_last[i] = 0.f;
    if (idx < 32) { g_arr0[idx] = 0u; g_flag0[idx] = 0u; g_arr1[idx] = 0u; g_flag1[idx] = 0u; }
}

// ---------------- fused reorder: slab [cta][k][16], col c: gate = c&3, unit_in_cta = c>>2 ----------------
__global__ void reorder_all(const float* __restrict__ encW0, const float* __restrict__ encW1,
                            const float* __restrict__ decW0, const float* __restrict__ decW1) {
    const size_t S0 = (size_t)512 * 2048, S1 = (size_t)1024 * 2048;
    const size_t total = 2 * S0 + 2 * S1;
    for (size_t idx = (size_t)blockIdx.x * blockDim.x + threadIdx.x; idx < total;
         idx += (size_t)gridDim.x * blockDim.x) {
        const float* src; float* dst; int K; size_t o = idx;
        if (o < S0)                { src = encW0 + (size_t)256 * 2048;  dst = g_Wr;               K = 512;  }
        else if (o < S0 + S1)      { o -= S0;      src = encW1;                      dst = g_Wr + S0;          K = 1024; }
        else if (o < 2 * S0 + S1)  { o -= S0 + S1; src = decW0 + (size_t)768 * 2048; dst = g_Wr + S0 + S1;     K = 512;  }
        else                       { o -= 2 * S0 + S1; src = decW1;                  dst = g_Wr + 2 * S0 + S1; K = 1024; }
        int slab = K * 16;
        int cta = (int)(o / slab);
        int rem = (int)(o - (size_t)cta * slab);
        int k = rem >> 4, c = rem & 15;
        dst[o] = src[(size_t)k * 2048 + (size_t)(c & 3) * 512 + cta * 4 + (c >> 2)];
    }
}

// ---------------- precompute GEMM: C[M,2048] = A[M,K] @ B[K,2048] (+bias), slab-col store ----------------
__global__ void __launch_bounds__(256, 1) gemm_pre(
    const float* __restrict__ A, int M, int K,
    const float* __restrict__ B, const float* __restrict__ bias,
    float* __restrict__ C)
{
    const int col0 = blockIdx.x * 128;
    __shared__ __align__(16) float As[128][33];
    __shared__ __align__(16) float Ws[32][128];
    const int tid = threadIdx.x;
    const int tc = tid & 31, rg = tid >> 5;

    float4 acc[16];
#pragma unroll
    for (int i = 0; i < 16; i++) acc[i] = make_float4(0.f, 0.f, 0.f, 0.f);

    for (int k0 = 0; k0 < K; k0 += 32) {
        for (int e = tid; e < 128 * 32; e += 256) {
            int r = e >> 5, kk = e & 31;
            As[r][kk] = (r < M) ? A[(size_t)r * K + k0 + kk] : 0.f;
        }
        for (int e = tid; e < 32 * 128; e += 256) {
            int kk = e >> 7, c = e & 127;
            Ws[kk][c] = B[(size_t)(k0 + kk) * 2048 + col0 + c];
        }
        __syncthreads();
#pragma unroll
        for (int kk = 0; kk < 32; kk++) {
            float4 w = *reinterpret_cast<const float4*>(&Ws[kk][tc * 4]);
#pragma unroll
            for (int r = 0; r < 16; r++) {
                float a = As[rg * 16 + r][kk];
                acc[r].x = fmaf(a, w.x, acc[r].x);
                acc[r].y = fmaf(a, w.y, acc[r].y);
                acc[r].z = fmaf(a, w.z, acc[r].z);
                acc[r].w = fmaf(a, w.w, acc[r].w);
            }
        }
        __syncthreads();
    }
#pragma unroll
    for (int r = 0; r < 16; r++) {
        int row = rg * 16 + r;
        if (row >= M) continue;
        float av[4] = {acc[r].x, acc[r].y, acc[r].z, acc[r].w};
#pragma unroll
        for (int q = 0; q < 4; q++) {
            int oc = col0 + tc * 4 + q;
            float val = av[q] + (bias ? bias[oc] : 0.f);
            int g = oc >> 9, u = oc & 511;
            int nc = (u >> 2) * 16 + (u & 3) * 4 + g;   // cta*16 + cp*4 + gate
            C[(size_t)row * 2048 + nc] = val;
        }
    }
}

// ================= decoupled layer chains =================
// thread: m = tid>>2 (batch row), cp = tid&3 (unit within CTA); acc = gates i,j,f,o

__global__ void __launch_bounds__(TPB, 2) encoder_kernel(
    const int* __restrict__ en_input, const int* __restrict__ en_len,
    const float* __restrict__ b1g)
{
    extern __shared__ float sm[];
    const int bid = blockIdx.x, tid = threadIdx.x;
    const int m = tid >> 2, cp = tid & 3;
    const int q0 = cp * 8;
    const int mylen = en_len[m];

    if (bid < 128) {
        // ---- layer-0 chain: K=512, 4 chunks, writes g_hist ----
        const int cta = bid, unit = cta * 4 + cp;
        float* ws = sm;
        float* xs = sm + 512 * 16;
        {
            const float4* wg = (const float4*)(g_Wr + (size_t)cta * (512 * 16));
            for (int i = tid; i < 512 * 4; i += TPB) ((float4*)ws)[i] = wg[i];
        }
        float c0 = 0.f, h0r = 0.f;
        __syncthreads();
#pragma unroll 1
        for (int t = 0; t < 256; ++t) {
            const float* hsrc = g_hist + (size_t)t * HS;
            int tok = en_input[m * 256 + t];
            float4 ez = *(const float4*)(g_embz_enc + (size_t)tok * 2048 + cta * 16 + cp * 4);
            float4 acc = make_float4(0.f, 0.f, 0.f, 0.f);
#pragma unroll 1
            for (int ch = 0; ch < 4; ++ch) {
                __syncthreads();
                fill_chunk(xs, hsrc + ch * 128, m, q0);
                __syncthreads();
                compute_chunk(xs + m * XSTF, ws + ch * (128 * 16), cp, acc);
            }
            bool valid = t < mylen;
            float zi = acc.x + ez.x, zj = acc.y + ez.y, zf = acc.z + ez.z, zo = acc.w + ez.w;
            float nc = c0 * sigmoidf_(zf + 1.0f) + sigmoidf_(zi) * tanhf(zj);
            float nh = tanhf(nc) * sigmoidf_(zo);
            if (valid) { c0 = nc; h0r = nh; }
            g_hist[(size_t)(t + 1) * HS + m * 512 + unit] = h0r;
            group_sync(&g_arr0[0], &g_flag0[0], (unsigned)(t + 1), 128u);
        }
        g_c0[m * 512 + unit] = c0;
    } else {
        // ---- layer-1 chain: K=1024 (hist[t+1] | h1prev), 8 chunks ----
        const int cta = bid - 128, unit = cta * 4 + cp;
        float* ws = sm;
        float* xs = sm + 1024 * 16;
        {
            const float4* wg = (const float4*)(g_Wr + (size_t)512 * 2048 + (size_t)cta * (1024 * 16));
            for (int i = tid; i < 1024 * 4; i += TPB) ((float4*)ws)[i] = wg[i];
        }
        float4 b1 = make_float4(b1g[0 * 512 + unit], b1g[1 * 512 + unit],
                                b1g[2 * 512 + unit], b1g[3 * 512 + unit]);
        float c1 = 0.f, h1r = 0.f;
        __syncthreads();
#pragma unroll 1
        for (int t = 0; t < 256; ++t) {
            wait_flag(&g_flag0[0], (unsigned)(t + 1));
            const float* h0cur  = g_hist + (size_t)(t + 1) * HS;
            const float* h1prev = g_h1 + ((t + 1) & 1) * HS;
            float4 acc = make_float4(0.f, 0.f, 0.f, 0.f);
#pragma unroll 1
            for (int ch = 0; ch < 8; ++ch) {
                const float* src = (ch < 4) ? (h0cur + ch * 128) : (h1prev + (ch - 4) * 128);
                __syncthreads();
                fill_chunk(xs, src, m, q0);
                __syncthreads();
                compute_chunk(xs + m * XSTF, ws + ch * (128 * 16), cp, acc);
            }
            bool valid = t < mylen;
            float zi = acc.x + b1.x, zj = acc.y + b1.y, zf = acc.z + b1.z, zo = acc.w + b1.w;
            float nc = c1 * sigmoidf_(zf + 1.0f) + sigmoidf_(zi) * tanhf(zj);
            float nh = tanhf(nc) * sigmoidf_(zo);
            if (valid) { c1 = nc; h1r = nh; g_en_last[m * 512 + unit] = nh; }
            g_h1[(t & 1) * HS + m * 512 + unit] = h1r;
            group_sync(&g_arr1[0], &g_flag1[0], (unsigned)(t + 1), 128u);
        }
        g_c1[m * 512 + unit] = c1;
    }
}

__global__ void __launch_bounds__(TPB, 2) decoder_kernel(
    const int* __restrict__ dec_input, const int* __restrict__ dec_len,
    const float* __restrict__ b1g)
{
    extern __shared__ float sm[];
    const int bid = blockIdx.x, tid = threadIdx.x;
    const int m = tid >> 2, cp = tid & 3;
    const int q0 = cp * 8;
    const int mylen = dec_len[m];

    if (bid < 128) {
        // ---- decoder layer-0 chain: s = 256+t, reads hist[s], writes hist[s+1] ----
        const int cta = bid, unit = cta * 4 + cp;
        float* ws = sm;
        float* xs = sm + 512 * 16;
        {
            const float4* wg = (const float4*)(g_Wr + (size_t)1536 * 2048 + (size_t)cta * (512 * 16));
            for (int i = tid; i < 512 * 4; i += TPB) ((float4*)ws)[i] = wg[i];
        }
        float4 el = *(const float4*)(g_enlz + (size_t)m * 2048 + cta * 16 + cp * 4);
        float c0 = __ldcg(&g_c0[m * 512 + unit]);
        float h0r = __ldcg(&g_hist[(size_t)256 * HS + m * 512 + unit]);
        __syncthreads();
#pragma unroll 1
        for (int t = 0; t < 256; ++t) {
            const unsigned s = 256u + (unsigned)t;
            const float* hsrc = g_hist + (size_t)s * HS;
            int tok = dec_input[m * 256 + t];
            float4 ez = *(const float4*)(g_embz_dec + (size_t)tok * 2048 + cta * 16 + cp * 4);
            float4 acc = make_float4(0.f, 0.f, 0.f, 0.f);
#pragma unroll 1
            for (int ch = 0; ch < 4; ++ch) {
                __syncthreads();
                fill_chunk(xs, hsrc + ch * 128, m, q0);
                __syncthreads();
                compute_chunk(xs + m * XSTF, ws + ch * (128 * 16), cp, acc);
            }
            bool valid = t < mylen;
            float zi = acc.x + ez.x + el.x, zj = acc.y + ez.y + el.y;
            float zf = acc.z + ez.z + el.z, zo = acc.w + ez.w + el.w;
            float nc = c0 * sigmoidf_(zf + 1.0f) + sigmoidf_(zi) * tanhf(zj);
            float nh = tanhf(nc) * sigmoidf_(zo);
            if (valid) { c0 = nc; h0r = nh; }
            g_hist[(size_t)(s + 1) * HS + m * 512 + unit] = h0r;
            group_sync(&g_arr0[0], &g_flag0[0], s + 1u, 128u);
        }
    } else {
        // ---- decoder layer-1 chain ----
        const int cta = bid - 128, unit = cta * 4 + cp;
        float* ws = sm;
        float* xs = sm + 1024 * 16;
        {
            const float4* wg = (const float4*)(g_Wr + (size_t)2048 * 2048 + (size_t)cta * (1024 * 16));
            for (int i = tid; i < 1024 * 4; i += TPB) ((float4*)ws)[i] = wg[i];
        }
        float4 b1 = make_float4(b1g[0 * 512 + unit], b1g[1 * 512 + unit],
                                b1g[2 * 512 + unit], b1g[3 * 512 + unit]);
        float c1 = __ldcg(&g_c1[m * 512 + unit]);
        float h1r = __ldcg(&g_h1[1 * HS + m * 512 + unit]);   // enc ended writing ping[255&1=1]
        __syncthreads();
#pragma unroll 1
        for (int t = 0; t < 256; ++t) {
            const unsigned s = 256u + (unsigned)t;
            wait_flag(&g_flag0[0], s + 1u);
            const float* h0cur  = g_hist + (size_t)(s + 1) * HS;
            const float* h1prev = g_h1 + ((s + 1) & 1) * HS;
            float4 acc = make_float4(0.f, 0.f, 0.f, 0.f);
#pragma unroll 1
            for (int ch = 0; ch < 8; ++ch) {
                const float* src = (ch < 4) ? (h0cur + ch * 128) : (h1prev + (ch - 4) * 128);
                __syncthreads();
                fill_chunk(xs, src, m, q0);
                __syncthreads();
                compute_chunk(xs + m * XSTF, ws + ch * (128 * 16), cp, acc);
            }
            bool valid = t < mylen;
            float zi = acc.x + b1.x, zj = acc.y + b1.y, zf = acc.z + b1.z, zo = acc.w + b1.w;
            float nc = c1 * sigmoidf_(zf + 1.0f) + sigmoidf_(zi) * tanhf(zj);
            float nh = tanhf(nc) * sigmoidf_(zo);
            if (valid) { c1 = nc; h1r = nh; }
            g_h1[(s & 1) * HS + m * 512 + unit] = h1r;
            g_dec_out[((size_t)m * 256 + t) * 512 + unit] = valid ? h1r : 0.f;
            group_sync(&g_arr1[0], &g_flag1[0], s + 1u, 128u);
        }
    }
}

// ---------------- projection: [16384,512] @ [512,128] + bias ----------------
__global__ void __launch_bounds__(256, 1) proj_kernel(
    const float* __restrict__ projW, const float* __restrict__ projb,
    float* __restrict__ out)
{
    const int row0 = blockIdx.x * 128;
    __shared__ __align__(16) float As[128][33];
    __shared__ __align__(16) float Ws[32][128];
    const int tid = threadIdx.x;
    const int tc = tid & 31, rg = tid >> 5;

    float4 acc[16];
#pragma unroll
    for (int i = 0; i < 16; i++) acc[i] = make_float4(0.f, 0.f, 0.f, 0.f);

    for (int k0 = 0; k0 < 512; k0 += 32) {
        for (int e = tid; e < 128 * 32; e += 256) {
            int r = e >> 5, kk = e & 31;
            As[r][kk] = g_dec_out[(size_t)(row0 + r) * 512 + k0 + kk];
        }
        for (int e = tid; e < 32 * 128; e += 256) {
            int kk = e >> 7, c = e & 127;
            Ws[kk][c] = projW[(size_t)(k0 + kk) * 128 + c];
        }
        __syncthreads();
#pragma unroll
        for (int kk = 0; kk < 32; kk++) {
            float4 w = *reinterpret_cast<const float4*>(&Ws[kk][tc * 4]);
#pragma unroll
            for (int r = 0; r < 16; r++) {
                float a = As[rg * 16 + r][kk];
                acc[r].x = fmaf(a, w.x, acc[r].x);
                acc[r].y = fmaf(a, w.y, acc[r].y);
                acc[r].z = fmaf(a, w.z, acc[r].z);
                acc[r].w = fmaf(a, w.w, acc[r].w);
            }
        }
        __syncthreads();
    }
    float4 pb = *reinterpret_cast<const float4*>(&projb[tc * 4]);
#pragma unroll
    for (int r = 0; r < 16; r++) {
        int row = row0 + rg * 16 + r;
        float4 v = make_float4(acc[r].x + pb.x, acc[r].y + pb.y,
                               acc[r].z + pb.z, acc[r].w + pb.w);
        *reinterpret_cast<float4*>(&out[(size_t)row * 128 + tc * 4]) = v;
    }
}

// ---------------- launch ----------------
#define SEQ_SMEM ((1024 * 16 + XSN) * 4)    // 99328 B -> 2 CTAs/SM

extern "C" void kernel_launch(void* const* d_in, const int* in_sizes, int n_in,
                              void* d_out, int out_size) {
    const int*   en_input  = (const int*)d_in[0];
    const int*   en_len    = (const int*)d_in[1];
    const int*   dec_input = (const int*)d_in[2];
    const int*   dec_len   = (const int*)d_in[3];
    const float* embed     = (const float*)d_in[4];
    const float* encW0     = (const float*)d_in[5];
    const float* encb0     = (const float*)d_in[6];
    const float* encW1     = (const float*)d_in[7];
    const float* encb1     = (const float*)d_in[8];
    const float* decW0     = (const float*)d_in[9];
    const float* decb0     = (const float*)d_in[10];
    const float* decW1     = (const float*)d_in[11];
    const float* decb1     = (const float*)d_in[12];
    const float* projW     = (const float*)d_in[13];
    const float* projb     = (const float*)d_in[14];
    float* out = (float*)d_out;

    float* embz_enc; cudaGetSymbolAddress((void**)&embz_enc, g_embz_enc);
    float* embz_dec; cudaGetSymbolAddress((void**)&embz_dec, g_embz_dec);
    float* enlz;     cudaGetSymbolAddress((void**)&enlz, g_enlz);
    float* en_last;  cudaGetSymbolAddress((void**)&en_last, g_en_last);

    cudaFuncSetAttribute(encoder_kernel, cudaFuncAttributeMaxDynamicSharedMemorySize, SEQ_SMEM);
    cudaFuncSetAttribute(decoder_kernel, cudaFuncAttributeMaxDynamicSharedMemorySize, SEQ_SMEM);

    init_kernel<<<128, 256>>>();                                        // idx 0
    reorder_all<<<1024, 256>>>(encW0, encW1, decW0, decW1);             // idx 1
    gemm_pre<<<16, 256>>>(embed, 128, 256, encW0, encb0, embz_enc);     // idx 2
    encoder_kernel<<<256, TPB, SEQ_SMEM>>>(en_input, en_len, encb1);    // idx 3  <- ncu slot
    gemm_pre<<<16, 256>>>(embed, 128, 256, decW0, decb0, embz_dec);     // idx 4
    gemm_pre<<<16, 256>>>(en_last, 64, 512, decW0 + (size_t)256 * 2048,
                          (const float*)nullptr, enlz);                 // idx 5
    decoder_kernel<<<256, TPB, SEQ_SMEM>>>(dec_input, dec_len, decb1);  // idx 6
    proj_kernel<<<128, 256>>>(projW, projb, out);                       // idx 7
}

// round 17
// speedup vs baseline: 3.9314x; 3.9314x over previous
#include <cuda_runtime.h>
#include <math.h>
#include <stdint.h>

#define NCTA 128
#define TPB  512
#define HS   (64 * 512)

// smem word-offsets (float/uint32 units)
#define S_ROW   274                       // words per 64-row bf16-pair tile row
#define XHI_W   0
#define XLO_W   17536                     // 64*274
#define RED_W   35072                     // 2*17536
#define SMEM_WORDS (RED_W + 64 * 16 * 17) // + red 17408 = 52480
#define SEQ_SMEM (SMEM_WORDS * 4)         // 209920 B

// ---------------- device scratch ----------------
__device__ float g_h0[2 * HS];
__device__ float g_h1[2 * HS];
__device__ float g_c0[HS];
__device__ float g_c1[HS];
__device__ float g_en_last[HS];
__device__ float g_embz_enc[128 * 2048];
__device__ float g_embz_dec[128 * 2048];
__device__ float g_enlz[64 * 2048];
__device__ float g_dec_out[64 * 256 * 512];
__device__ __align__(128) unsigned g_arrive[32];
__device__ __align__(128) unsigned g_flag[32];

__device__ __forceinline__ float sigmoidf_(float x) { return 1.0f / (1.0f + __expf(-x)); }

__device__ __forceinline__ void grid_bar(unsigned step) {
    __syncthreads();
    if (threadIdx.x == 0) {
        __threadfence();
        unsigned prev = atomicAdd(&g_arrive[0], 1u);
        if (prev == step * NCTA - 1u) {
            asm volatile("st.release.gpu.global.u32 [%0], %1;" :: "l"(&g_flag[0]), "r"(step) : "memory");
        } else {
            unsigned v;
            while (true) {
                asm volatile("ld.acquire.gpu.global.u32 %0, [%1];" : "=r"(v) : "l"(&g_flag[0]) : "memory");
                if ((int)(v - step) >= 0) break;
                __nanosleep(64);
            }
        }
    }
    __syncthreads();
}

#define MMA16816(Cc, A0, A1, A2, A3, B0, B1) \
    asm volatile("mma.sync.aligned.m16n8k16.row.col.f32.bf16.bf16.f32 " \
        "{%0,%1,%2,%3}, {%4,%5,%6,%7}, {%8,%9}, {%0,%1,%2,%3};" \
        : "+f"(Cc[0]), "+f"(Cc[1]), "+f"(Cc[2]), "+f"(Cc[3]) \
        : "r"(A0), "r"(A1), "r"(A2), "r"(A3), "r"(B0), "r"(B1))

// pack two floats -> bf16x2 (lo = first), plus residual pack
__device__ __forceinline__ uint32_t pack_hi(float x0, float x1) {
    uint32_t h;
    asm("cvt.rn.bf16x2.f32 %0, %1, %2;" : "=r"(h) : "f"(x1), "f"(x0));
    return h;
}
__device__ __forceinline__ uint32_t pack_lo(float x0, float x1, uint32_t h) {
    float r0 = x0 - __uint_as_float(h << 16);
    float r1 = x1 - __uint_as_float(h & 0xFFFF0000u);
    uint32_t l;
    asm("cvt.rn.bf16x2.f32 %0, %1, %2;" : "=r"(l) : "f"(r1), "f"(r0));
    return l;
}

// build one B fragment pair (hi & lo) for (global k-tile ktg, n-tile nt)
__device__ __forceinline__ void build_bfrag(const float* __restrict__ W, int ktg, int nt,
                                            int cta, int g, int t4,
                                            uint32_t bh[2], uint32_t bl[2]) {
    int c = nt * 8 + g;
    int wcol = (c & 3) * 512 + cta * 4 + (c >> 2);
#pragma unroll
    for (int r = 0; r < 2; ++r) {
        int k0 = ktg * 16 + t4 * 2 + r * 8;
        float w0 = W[(size_t)k0 * 2048 + wcol];
        float w1 = W[(size_t)(k0 + 1) * 2048 + wcol];
        uint32_t h = pack_hi(w0, w1);
        bh[r] = h;
        bl[r] = pack_lo(w0, w1, h);
    }
}

// one 512-k round: fill smem x tiles (bf16 hi/lo) from src, then mma warp k-slices
template <int BASE>
__device__ __forceinline__ void do_round(
    uint32_t* __restrict__ smw, const float* __restrict__ src,
    const uint32_t (&bh)[6][2][2], const uint32_t (&bl)[6][2][2],
    float (&C)[4][2][4], int wid, int g, int t4, int row, int seg)
{
    __syncthreads();   // previous round's smem-x reads complete
    // fill: thread covers row, k = j*32 + seg*4 .. +3
#pragma unroll
    for (int j = 0; j < 16; ++j) {
        float4 v = __ldcg((const float4*)(src + row * 512 + j * 32 + seg * 4));
        uint32_t h01 = pack_hi(v.x, v.y);
        uint32_t h23 = pack_hi(v.z, v.w);
        uint32_t l01 = pack_lo(v.x, v.y, h01);
        uint32_t l23 = pack_lo(v.z, v.w, h23);
        int w = row * S_ROW + j * 16 + seg * 2;
        *(uint2*)(smw + XHI_W + w) = make_uint2(h01, h23);
        *(uint2*)(smw + XLO_W + w) = make_uint2(l01, l23);
    }
    __syncthreads();
    // mma: warp owns local k-tiles {wid, wid+16}
#pragma unroll
    for (int s = 0; s < 2; ++s) {
        int kw = (wid + 16 * s) * 8;
#pragma unroll
        for (int mt = 0; mt < 4; ++mt) {
            int m0 = mt * 16 + g;
            uint32_t a0 = smw[XHI_W + m0 * S_ROW + kw + t4];
            uint32_t a1 = smw[XHI_W + (m0 + 8) * S_ROW + kw + t4];
            uint32_t a2 = smw[XHI_W + m0 * S_ROW + kw + 4 + t4];
            uint32_t a3 = smw[XHI_W + (m0 + 8) * S_ROW + kw + 4 + t4];
            MMA16816(C[mt][0], a0, a1, a2, a3, bh[BASE + s][0][0], bh[BASE + s][0][1]);
            MMA16816(C[mt][1], a0, a1, a2, a3, bh[BASE + s][1][0], bh[BASE + s][1][1]);
            MMA16816(C[mt][0], a0, a1, a2, a3, bl[BASE + s][0][0], bl[BASE + s][0][1]);
            MMA16816(C[mt][1], a0, a1, a2, a3, bl[BASE + s][1][0], bl[BASE + s][1][1]);
            uint32_t e0 = smw[XLO_W + m0 * S_ROW + kw + t4];
            uint32_t e1 = smw[XLO_W + (m0 + 8) * S_ROW + kw + t4];
            uint32_t e2 = smw[XLO_W + m0 * S_ROW + kw + 4 + t4];
            uint32_t e3 = smw[XLO_W + (m0 + 8) * S_ROW + kw + 4 + t4];
            MMA16816(C[mt][0], e0, e1, e2, e3, bh[BASE + s][0][0], bh[BASE + s][0][1]);
            MMA16816(C[mt][1], e0, e1, e2, e3, bh[BASE + s][1][0], bh[BASE + s][1][1]);
        }
    }
}

__device__ __forceinline__ void write_C(float* __restrict__ red, float (&C)[4][2][4],
                                        int wid, int g, int t4) {
#pragma unroll
    for (int mt = 0; mt < 4; ++mt)
#pragma unroll
        for (int nt = 0; nt < 2; ++nt) {
            int m0 = mt * 16 + g, cb = nt * 8 + t4 * 2;
            red[(m0 * 16 + cb) * 17 + wid]           = C[mt][nt][0];
            red[(m0 * 16 + cb + 1) * 17 + wid]       = C[mt][nt][1];
            red[((m0 + 8) * 16 + cb) * 17 + wid]     = C[mt][nt][2];
            red[((m0 + 8) * 16 + cb + 1) * 17 + wid] = C[mt][nt][3];
        }
}

__device__ __forceinline__ void reduce16(float* __restrict__ red, int tid) {
    __syncthreads();
#pragma unroll
    for (int rr = 0; rr < 2; ++rr) {
        int base = (tid + rr * 512) * 17;
        float s = 0.f;
#pragma unroll
        for (int i = 0; i < 16; ++i) s += red[base + i];
        red[base + 16] = s;
    }
    __syncthreads();
}

// ---------------- init ----------------
__global__ void init_kernel() {
    int idx = blockIdx.x * blockDim.x + threadIdx.x;
    int stride = gridDim.x * blockDim.x;
    for (int i = idx; i < 2 * HS; i += stride) { g_h0[i] = 0.f; g_h1[i] = 0.f; }
    for (int i = idx; i < HS; i += stride) g_en_last[i] = 0.f;
    if (idx < 32) { g_arrive[idx] = 0u; g_flag[idx] = 0u; }
}

// ---------------- precompute GEMM: C[M,2048] = A@B (+bias), col layout cta*16 + uu*4 + gate ----------------
__global__ void __launch_bounds__(256, 1) gemm_pre(
    const float* __restrict__ A, int M, int K,
    const float* __restrict__ B, const float* __restrict__ bias,
    float* __restrict__ C)
{
    const int col0 = blockIdx.x * 128;
    __shared__ __align__(16) float As[128][33];
    __shared__ __align__(16) float Ws[32][128];
    const int tid = threadIdx.x;
    const int tc = tid & 31, rg = tid >> 5;

    float4 acc[16];
#pragma unroll
    for (int i = 0; i < 16; i++) acc[i] = make_float4(0.f, 0.f, 0.f, 0.f);

    for (int k0 = 0; k0 < K; k0 += 32) {
        for (int e = tid; e < 128 * 32; e += 256) {
            int r = e >> 5, kk = e & 31;
            As[r][kk] = (r < M) ? A[(size_t)r * K + k0 + kk] : 0.f;
        }
        for (int e = tid; e < 32 * 128; e += 256) {
            int kk = e >> 7, c = e & 127;
            Ws[kk][c] = B[(size_t)(k0 + kk) * 2048 + col0 + c];
        }
        __syncthreads();
#pragma unroll
        for (int kk = 0; kk < 32; kk++) {
            float4 w = *reinterpret_cast<const float4*>(&Ws[kk][tc * 4]);
#pragma unroll
            for (int r = 0; r < 16; r++) {
                float a = As[rg * 16 + r][kk];
                acc[r].x = fmaf(a, w.x, acc[r].x);
                acc[r].y = fmaf(a, w.y, acc[r].y);
                acc[r].z = fmaf(a, w.z, acc[r].z);
                acc[r].w = fmaf(a, w.w, acc[r].w);
            }
        }
        __syncthreads();
    }
#pragma unroll
    for (int r = 0; r < 16; r++) {
        int row = rg * 16 + r;
        if (row >= M) continue;
        float av[4] = {acc[r].x, acc[r].y, acc[r].z, acc[r].w};
#pragma unroll
        for (int q = 0; q < 4; q++) {
            int oc = col0 + tc * 4 + q;
            float val = av[q] + (bias ? bias[oc] : 0.f);
            int g = oc >> 9, u = oc & 511;
            int nc = (u >> 2) * 16 + (u & 3) * 4 + g;
            C[(size_t)row * 2048 + nc] = val;
        }
    }
}

// ================= mma.sync persistent sequence kernel =================
__global__ void __launch_bounds__(TPB, 1) seq_kernel(
    const int* __restrict__ tokens, const int* __restrict__ lens,
    const float* __restrict__ b1g, const float* __restrict__ embz,
    const float* __restrict__ elz,
    const float* __restrict__ W0, const float* __restrict__ W1,
    unsigned sbase, int is_dec)
{
    extern __shared__ float sm[];
    uint32_t* smw = (uint32_t*)sm;
    float* red = sm + RED_W;

    const int cta = blockIdx.x, tid = threadIdx.x;
    const int wid = tid >> 5, lane = tid & 31;
    const int g = lane >> 2, t4 = lane & 3;
    const int row = tid >> 3, seg = tid & 7;

    // B fragments: slots 0-1 = layer0 (tiles wid, wid+16);
    //              slots 2-5 = layer1 (tiles wid, wid+16, 32+wid, 48+wid)
    uint32_t bh[6][2][2], bl[6][2][2];
#pragma unroll
    for (int s = 0; s < 2; ++s)
#pragma unroll
        for (int nt = 0; nt < 2; ++nt)
            build_bfrag(W0, wid + 16 * s, nt, cta, g, t4, bh[s][nt], bl[s][nt]);
#pragma unroll
    for (int q = 0; q < 4; ++q)
#pragma unroll
        for (int nt = 0; nt < 2; ++nt)
            build_bfrag(W1, wid + 16 * (q & 1) + 32 * (q >> 1), nt, cta, g, t4,
                        bh[2 + q][nt], bl[2 + q][nt]);

    // gate-thread state (tid < 256): (m, unit uu)
    const int m_g = tid >> 2, uu = tid & 3;
    float cc0 = 0.f, cc1 = 0.f, hh0 = 0.f, hh1 = 0.f;
    float b1v[4] = {0, 0, 0, 0}, elv[4] = {0, 0, 0, 0};
    int mylen = 0;
    if (tid < 256) {
        mylen = lens[m_g];
#pragma unroll
        for (int g4 = 0; g4 < 4; ++g4) b1v[g4] = b1g[g4 * 512 + cta * 4 + uu];
        if (elz) {
#pragma unroll
            for (int g4 = 0; g4 < 4; ++g4)
                elv[g4] = elz[(size_t)m_g * 2048 + cta * 16 + uu * 4 + g4];
        }
        if (is_dec) {
            cc0 = g_c0[m_g * 512 + cta * 4 + uu];
            cc1 = g_c1[m_g * 512 + cta * 4 + uu];
            hh0 = g_h0[HS + m_g * 512 + cta * 4 + uu];   // encoder t=255 wrote buffer 1
            hh1 = g_h1[HS + m_g * 512 + cta * 4 + uu];
        }
    }

#pragma unroll 1
    for (int t = 0; t < 256; ++t) {
        const float* h0prev = g_h0 + ((t + 1) & 1) * HS;
        float*       h0cur  = g_h0 + (t & 1) * HS;
        const float* h1prev = g_h1 + ((t + 1) & 1) * HS;
        float*       h1cur  = g_h1 + (t & 1) * HS;

        // ---- phase A: layer 0, K=512 ----
        float C[4][2][4];
#pragma unroll
        for (int a = 0; a < 4; ++a)
#pragma unroll
            for (int b = 0; b < 2; ++b)
#pragma unroll
                for (int c = 0; c < 4; ++c) C[a][b][c] = 0.f;
        do_round<0>(smw, h0prev, bh, bl, C, wid, g, t4, row, seg);
        write_C(red, C, wid, g, t4);
        reduce16(red, tid);
        if (tid < 256) {
            bool valid = t < mylen;
            int tok = tokens[m_g * 256 + t];
            const float* ez = embz + (size_t)tok * 2048 + cta * 16 + uu * 4;
            float z[4];
#pragma unroll
            for (int g4 = 0; g4 < 4; ++g4)
                z[g4] = red[(m_g * 16 + uu * 4 + g4) * 17 + 16] + ez[g4] + elv[g4];
            float nc = cc0 * sigmoidf_(z[2] + 1.0f) + sigmoidf_(z[0]) * tanhf(z[1]);
            float nh = tanhf(nc) * sigmoidf_(z[3]);
            if (valid) { cc0 = nc; hh0 = nh; }
            h0cur[m_g * 512 + cta * 4 + uu] = hh0;
        }
        grid_bar(sbase + (unsigned)t + 1u);

        // ---- phase B: layer 1, K=1024 (round0: h0cur, round1: h1prev) ----
#pragma unroll
        for (int a = 0; a < 4; ++a)
#pragma unroll
            for (int b = 0; b < 2; ++b)
#pragma unroll
                for (int c = 0; c < 4; ++c) C[a][b][c] = 0.f;
        do_round<2>(smw, h0cur, bh, bl, C, wid, g, t4, row, seg);
        do_round<4>(smw, h1prev, bh, bl, C, wid, g, t4, row, seg);
        write_C(red, C, wid, g, t4);
        reduce16(red, tid);
        if (tid < 256) {
            bool valid = t < mylen;
            float z[4];
#pragma unroll
            for (int g4 = 0; g4 < 4; ++g4)
                z[g4] = red[(m_g * 16 + uu * 4 + g4) * 17 + 16] + b1v[g4];
            float nc = cc1 * sigmoidf_(z[2] + 1.0f) + sigmoidf_(z[0]) * tanhf(z[1]);
            float nh = tanhf(nc) * sigmoidf_(z[3]);
            if (valid) { cc1 = nc; hh1 = nh; }
            h1cur[m_g * 512 + cta * 4 + uu] = hh1;
            if (!is_dec) {
                if (valid) g_en_last[m_g * 512 + cta * 4 + uu] = hh1;
            } else {
                g_dec_out[((size_t)m_g * 256 + t) * 512 + cta * 4 + uu] = valid ? hh1 : 0.f;
            }
        }
    }
    if (!is_dec && tid < 256) {
        g_c0[m_g * 512 + cta * 4 + uu] = cc0;
        g_c1[m_g * 512 + cta * 4 + uu] = cc1;
    }
}

// ---------------- projection: [16384,512] @ [512,128] + bias ----------------
__global__ void __launch_bounds__(256, 1) proj_kernel(
    const float* __restrict__ projW, const float* __restrict__ projb,
    float* __restrict__ out)
{
    const int row0 = blockIdx.x * 128;
    __shared__ __align__(16) float As[128][33];
    __shared__ __align__(16) float Ws[32][128];
    const int tid = threadIdx.x;
    const int tc = tid & 31, rg = tid >> 5;

    float4 acc[16];
#pragma unroll
    for (int i = 0; i < 16; i++) acc[i] = make_float4(0.f, 0.f, 0.f, 0.f);

    for (int k0 = 0; k0 < 512; k0 += 32) {
        for (int e = tid; e < 128 * 32; e += 256) {
            int r = e >> 5, kk = e & 31;
            As[r][kk] = g_dec_out[(size_t)(row0 + r) * 512 + k0 + kk];
        }
        for (int e = tid; e < 32 * 128; e += 256) {
            int kk = e >> 7, c = e & 127;
            Ws[kk][c] = projW[(size_t)(k0 + kk) * 128 + c];
        }
        __syncthreads();
#pragma unroll
        for (int kk = 0; kk < 32; kk++) {
            float4 w = *reinterpret_cast<const float4*>(&Ws[kk][tc * 4]);
#pragma unroll
            for (int r = 0; r < 16; r++) {
                float a = As[rg * 16 + r][kk];
                acc[r].x = fmaf(a, w.x, acc[r].x);
                acc[r].y = fmaf(a, w.y, acc[r].y);
                acc[r].z = fmaf(a, w.z, acc[r].z);
                acc[r].w = fmaf(a, w.w, acc[r].w);
            }
        }
        __syncthreads();
    }
    float4 pb = *reinterpret_cast<const float4*>(&projb[tc * 4]);
#pragma unroll
    for (int r = 0; r < 16; r++) {
        int rw = row0 + rg * 16 + r;
        float4 v = make_float4(acc[r].x + pb.x, acc[r].y + pb.y,
                               acc[r].z + pb.z, acc[r].w + pb.w);
        *reinterpret_cast<float4*>(&out[(size_t)rw * 128 + tc * 4]) = v;
    }
}

// ---------------- launch ----------------
extern "C" void kernel_launch(void* const* d_in, const int* in_sizes, int n_in,
                              void* d_out, int out_size) {
    const int*   en_input  = (const int*)d_in[0];
    const int*   en_len    = (const int*)d_in[1];
    const int*   dec_input = (const int*)d_in[2];
    const int*   dec_len   = (const int*)d_in[3];
    const float* embed     = (const float*)d_in[4];
    const float* encW0     = (const float*)d_in[5];
    const float* encb0     = (const float*)d_in[6];
    const float* encW1     = (const float*)d_in[7];
    const float* encb1     = (const float*)d_in[8];
    const float* decW0     = (const float*)d_in[9];
    const float* decb0     = (const float*)d_in[10];
    const float* decW1     = (const float*)d_in[11];
    const float* decb1     = (const float*)d_in[12];
    const float* projW     = (const float*)d_in[13];
    const float* projb     = (const float*)d_in[14];
    float* out = (float*)d_out;

    float* embz_enc; cudaGetSymbolAddress((void**)&embz_enc, g_embz_enc);
    float* embz_dec; cudaGetSymbolAddress((void**)&embz_dec, g_embz_dec);
    float* enlz;     cudaGetSymbolAddress((void**)&enlz, g_enlz);
    float* en_last;  cudaGetSymbolAddress((void**)&en_last, g_en_last);

    cudaFuncSetAttribute(seq_kernel, cudaFuncAttributeMaxDynamicSharedMemorySize, SEQ_SMEM);

    init_kernel<<<128, 256>>>();                                         // idx 0
    gemm_pre<<<16, 256>>>(embed, 128, 256, encW0, encb0, embz_enc);      // idx 1
    gemm_pre<<<16, 256>>>(embed, 128, 256, decW0, decb0, embz_dec);      // idx 2
    seq_kernel<<<NCTA, TPB, SEQ_SMEM>>>(en_input, en_len, encb1, embz_enc,
                                        (const float*)nullptr,
                                        encW0 + (size_t)256 * 2048, encW1,
                                        0u, 0);                          // idx 3 (ncu slot)
    gemm_pre<<<16, 256>>>(en_last, 64, 512, decW0 + (size_t)256 * 2048,
                          (const float*)nullptr, enlz);                  // idx 4
    seq_kernel<<<NCTA, TPB, SEQ_SMEM>>>(dec_input, dec_len, decb1, embz_dec,
                                        enlz, decW0 + (size_t)768 * 2048, decW1,
                                        256u, 1);                        // idx 5
    proj_kernel<<<128, 256>>>(projW, projb, out);                        // idx 6
}